// round 6
// baseline (speedup 1.0000x reference)
#include <cuda_runtime.h>
#include <cstdint>

#define BATCHN 64
#define FEAT   64
#define INF    64
#define NP     8
#define NCELL  256
#define NSYM   2048
#define NK2    9          // rfft half-plane: k2 in [0,8]
#define NFREQ  144        // 16 * 9
#define IPD    512        // INF * NP
#define FQD    512        // FEAT * NP

// -------- device scratch (no dynamic allocation allowed) --------
__device__ float2 g_xf[(size_t)NFREQ * BATCHN * IPD];   // [k][b][ip]
__device__ float2 g_kf[(size_t)NFREQ * IPD * FQD];      // [k][ip][fq]  (~302 MB)
__device__ float2 g_yf[(size_t)NFREQ * BATCHN * FQD];   // [k][b][fq]
__device__ unsigned short g_pt16[NP * NSYM];

// cos/sin of 2*pi*m/16
__constant__ float CTW16[16] = {
    1.0f,  0.92387953251f,  0.70710678119f,  0.38268343236f,
    0.0f, -0.38268343236f, -0.70710678119f, -0.92387953251f,
   -1.0f, -0.92387953251f, -0.70710678119f, -0.38268343236f,
    0.0f,  0.38268343236f,  0.70710678119f,  0.92387953251f };
__constant__ float STW16[16] = {
    0.0f,  0.38268343236f,  0.70710678119f,  0.92387953251f,
    1.0f,  0.92387953251f,  0.70710678119f,  0.38268343236f,
    0.0f, -0.38268343236f, -0.70710678119f, -0.92387953251f,
   -1.0f, -0.92387953251f, -0.70710678119f, -0.38268343236f };

// ============ K0: product_table (int32 OR int64) -> uint16 ============
// JAX without x64 silently emits int32 for a requested int64 randint.
// Detect layout: if the buffer really is int64 (values < 2048, nonneg),
// every odd int32 word (high half) is zero. For genuine int32 data the odd
// words are random in [0,2048): all-zero probability ~2048^-8192.
// Single block; scans only the first NP*NSYM int32 words (in-bounds both ways).
__global__ __launch_bounds__(256) void k0_pt(const void* __restrict__ pt_raw) {
    __shared__ int odd_nonzero;
    const int* p32 = (const int*)pt_raw;
    int tid = threadIdx.x;
    if (tid == 0) odd_nonzero = 0;
    __syncthreads();
    int local = 0;
    for (int t = tid; t < (NP * NSYM) / 2; t += 256) local |= p32[2 * t + 1];
    if (local) odd_nonzero = 1;   // benign race: any writer sets 1
    __syncthreads();
    if (odd_nonzero) {            // int32 layout
        for (int t = tid; t < NP * NSYM; t += 256)
            g_pt16[t] = (unsigned short)p32[t];
    } else {                      // genuine int64 layout
        const long long* p64 = (const long long*)pt_raw;
        for (int t = tid; t < NP * NSYM; t += 256)
            g_pt16[t] = (unsigned short)p64[t];
    }
}

// ============ K1: forward rfft2 of x images ============
// block = (b, i); 8 images (p = 0..7), each 16x16 real -> 16x9 complex
__global__ __launch_bounds__(256) void k1_xfft(const float* __restrict__ x) {
    int bi = blockIdx.x;
    int b  = bi >> 6;
    int i  = bi & 63;
    __shared__ float  xs[NSYM];
    __shared__ float2 s1[NP * 145];     // [p][c1*9+k2], padded
    __shared__ float2 tw[16];
    int tid = threadIdx.x;
    if (tid < 16) tw[tid] = make_float2(CTW16[tid], STW16[tid]);
    for (int t = tid; t < NSYM; t += 256) xs[t] = x[(size_t)bi * NSYM + t];
    __syncthreads();

    // stage 1: over c2 (real input): S1[p][c1][k2] = sum_c2 g * e^{-i 2pi k2 c2/16}
    for (int idx = tid; idx < NP * 16 * NK2; idx += 256) {
        int p  = idx / 144;
        int r  = idx - p * 144;
        int c1 = r / 9;
        int k2 = r - c1 * 9;
        float2 acc = make_float2(0.f, 0.f);
#pragma unroll
        for (int c2 = 0; c2 < 16; c2++) {
            float  g = xs[(((c1 << 4) + c2) << 3) + p];
            float2 w = tw[(k2 * c2) & 15];
            acc.x += g * w.x;
            acc.y -= g * w.y;
        }
        s1[p * 145 + c1 * 9 + k2] = acc;
    }
    __syncthreads();

    // stage 2: over c1 (complex): out[k1][k2] = sum_c1 S1 * e^{-i 2pi k1 c1/16}
    for (int idx = tid; idx < NP * 16 * NK2; idx += 256) {
        int p  = idx & 7;
        int r  = idx >> 3;
        int k1 = r / 9;
        int k2 = r - k1 * 9;
        float2 acc = make_float2(0.f, 0.f);
#pragma unroll
        for (int c1 = 0; c1 < 16; c1++) {
            float2 v = s1[p * 145 + c1 * 9 + k2];
            float2 w = tw[(k1 * c1) & 15];
            acc.x += v.x * w.x + v.y * w.y;
            acc.y += v.y * w.x - v.x * w.y;
        }
        g_xf[((size_t)(k1 * 9 + k2) * BATCHN + b) * IPD + (i << 3) + p] = acc;
    }
}

// ============ K2: gather + forward rfft2 of kernel images ============
// block = (f, i); loop p chunks; images (q = 0..7) per chunk
__global__ __launch_bounds__(256) void k2_kfft(const float* __restrict__ kern) {
    int fi = blockIdx.x;
    int f  = fi >> 6;
    int i  = fi & 63;
    __shared__ float  krow[NSYM];
    __shared__ unsigned short ptp[NSYM];
    __shared__ float  g8[NP * NCELL];   // [q][d]
    __shared__ float2 s1[NP * 145];     // [q][c1*9+k2] padded
    __shared__ float2 tw[16];
    int tid = threadIdx.x;
    if (tid < 16) tw[tid] = make_float2(CTW16[tid], STW16[tid]);
    for (int t = tid; t < NSYM; t += 256) krow[t] = kern[(size_t)fi * NSYM + t];

    for (int p = 0; p < NP; p++) {
        __syncthreads();  // protect ptp/g8/s1 reuse across iterations
        for (int t = tid; t < NSYM; t += 256) ptp[t] = g_pt16[p * NSYM + t];
        __syncthreads();
        // gather: g8[q][d] = krow[ pt[p][d*8+q] ]
        for (int idx = tid; idx < NSYM; idx += 256) {
            int d = idx >> 3;
            int q = idx & 7;
            g8[q * NCELL + d] = krow[ptp[idx]];
        }
        __syncthreads();
        // stage 1
        for (int idx = tid; idx < NP * 16 * NK2; idx += 256) {
            int q  = idx / 144;
            int r  = idx - q * 144;
            int c1 = r / 9;
            int k2 = r - c1 * 9;
            float2 acc = make_float2(0.f, 0.f);
#pragma unroll
            for (int c2 = 0; c2 < 16; c2++) {
                float  g = g8[q * NCELL + (c1 << 4) + c2];
                float2 w = tw[(k2 * c2) & 15];
                acc.x += g * w.x;
                acc.y -= g * w.y;
            }
            s1[q * 145 + c1 * 9 + k2] = acc;
        }
        __syncthreads();
        // stage 2 + global write (q = idx&7 -> 64B coalesced segments)
        for (int idx = tid; idx < NP * 16 * NK2; idx += 256) {
            int q  = idx & 7;
            int r  = idx >> 3;
            int k1 = r / 9;
            int k2 = r - k1 * 9;
            float2 acc = make_float2(0.f, 0.f);
#pragma unroll
            for (int c1 = 0; c1 < 16; c1++) {
                float2 v = s1[q * 145 + c1 * 9 + k2];
                float2 w = tw[(k1 * c1) & 15];
                acc.x += v.x * w.x + v.y * w.y;
                acc.y += v.y * w.x - v.x * w.y;
            }
            g_kf[((size_t)(k1 * 9 + k2) * IPD + (i << 3) + p) * FQD + (f << 3) + q] = acc;
        }
    }
}

// ============ K3: per-frequency complex GEMM ============
// Y[k][b][fq] = sum_ip X[k][b][ip] * W[k][ip][fq]
// grid = (144 freqs, 8 N-tiles of 64), block 256, 64x64 tile, 4x4 cplx acc/thread
__global__ __launch_bounds__(256) void k3_gemm() {
    int kidx = blockIdx.x;
    int n0   = blockIdx.y << 6;
    __shared__ __align__(16) float2 Xs[64][20];  // [b][kk], stride 20: aligned float4 stores
    __shared__ __align__(16) float2 Ws[16][64];  // [kk][col]
    int tid = threadIdx.x;
    int tx  = tid & 15;
    int ty  = tid >> 4;

    float2 acc[4][4];
#pragma unroll
    for (int r = 0; r < 4; r++)
#pragma unroll
        for (int c = 0; c < 4; c++) acc[r][c] = make_float2(0.f, 0.f);

    const float4* Xg4 = (const float4*)(g_xf + (size_t)kidx * BATCHN * IPD);
    const float4* Wg4 = (const float4*)(g_kf + (size_t)kidx * IPD * FQD + n0);

    for (int k0 = 0; k0 < IPD; k0 += 16) {
        // stage X: 64 b-rows x 8 float4 (16 float2) per chunk
#pragma unroll
        for (int it = 0; it < 2; it++) {
            int u = tid + (it << 8);             // 0..511
            int b = u >> 3;
            int j = u & 7;                        // float4 within chunk
            float4 v = Xg4[((size_t)b * IPD + k0) / 2 + j];
            *(float4*)&Xs[b][2 * j] = v;
        }
        // stage W: 16 kk-rows x 32 float4 (64 float2)
#pragma unroll
        for (int it = 0; it < 2; it++) {
            int u  = tid + (it << 8);            // 0..511
            int kk = u >> 5;
            int j  = u & 31;
            float4 v = Wg4[((size_t)(k0 + kk) * FQD) / 2 + j];
            *(float4*)&Ws[kk][2 * j] = v;
        }
        __syncthreads();
#pragma unroll
        for (int kk = 0; kk < 16; kk++) {
            float2 a[4], w[4];
#pragma unroll
            for (int r = 0; r < 4; r++) a[r] = Xs[ty + (r << 4)][kk];
#pragma unroll
            for (int c = 0; c < 4; c++) w[c] = Ws[kk][tx + (c << 4)];
#pragma unroll
            for (int r = 0; r < 4; r++)
#pragma unroll
                for (int c = 0; c < 4; c++) {
                    acc[r][c].x += a[r].x * w[c].x - a[r].y * w[c].y;
                    acc[r][c].y += a[r].x * w[c].y + a[r].y * w[c].x;
                }
        }
        __syncthreads();
    }

    float2* Yg = g_yf + (size_t)kidx * BATCHN * FQD + n0;
#pragma unroll
    for (int r = 0; r < 4; r++)
#pragma unroll
        for (int c = 0; c < 4; c++)
            Yg[(size_t)(ty + (r << 4)) * FQD + tx + (c << 4)] = acc[r][c];
}

// ============ K4: inverse rfft2 (hermitian weights) + bias ============
// block = (b, f); 8 images (q)
__global__ __launch_bounds__(256) void k4_inv(const float* __restrict__ bias,
                                              float* __restrict__ out) {
    int bf = blockIdx.x;
    int b  = bf >> 6;
    int f  = bf & 63;
    __shared__ float2 ys[NP * NFREQ];   // [q][kidx]
    __shared__ float2 T[NP * 145];      // [q][c1*9+k2] padded
    __shared__ float2 tw[16];
    int tid = threadIdx.x;
    if (tid < 16) tw[tid] = make_float2(CTW16[tid], STW16[tid]);

    // load Y: q = idx&7 -> 8 consecutive float2 reads per kidx
    for (int idx = tid; idx < NP * NFREQ; idx += 256) {
        int kidx = idx >> 3;
        int q    = idx & 7;
        ys[q * NFREQ + kidx] =
            g_yf[((size_t)kidx * BATCHN + b) * FQD + (f << 3) + q];
    }
    __syncthreads();

    // stage A: over k1 (inverse): T[c1][k2] = sum_k1 Y * e^{+i 2pi k1 c1/16}
    for (int idx = tid; idx < NP * 16 * NK2; idx += 256) {
        int q  = idx / 144;
        int r  = idx - q * 144;
        int c1 = r / 9;
        int k2 = r - c1 * 9;
        float2 acc = make_float2(0.f, 0.f);
#pragma unroll
        for (int k1 = 0; k1 < 16; k1++) {
            float2 v = ys[q * NFREQ + k1 * 9 + k2];
            float2 w = tw[(k1 * c1) & 15];
            acc.x += v.x * w.x - v.y * w.y;
            acc.y += v.x * w.y + v.y * w.x;
        }
        T[q * 145 + c1 * 9 + k2] = acc;
    }
    __syncthreads();

    // stage B: real output with hermitian weights; idx == c*8+q -> coalesced store
    float bv = bias[f];
    for (int idx = tid; idx < NSYM; idx += 256) {
        int c  = idx >> 3;
        int q  = idx & 7;
        int c1 = c >> 4;
        int c2 = c & 15;
        float acc = 0.f;
#pragma unroll
        for (int k2 = 0; k2 < NK2; k2++) {
            float2 v  = T[q * 145 + c1 * 9 + k2];
            float2 w  = tw[(k2 * c2) & 15];
            float  wt = (k2 == 0 || k2 == 8) ? 1.f : 2.f;
            acc += wt * (v.x * w.x - v.y * w.y);
        }
        out[(size_t)bf * NSYM + idx] = acc * (1.f / 256.f) + bv;
    }
}

// ============ launch ============
extern "C" void kernel_launch(void* const* d_in, const int* in_sizes, int n_in,
                              void* d_out, int out_size) {
    const float* x    = (const float*)d_in[0];
    const float* kern = (const float*)d_in[1];
    const float* bias = (const float*)d_in[2];
    const void*  pt   = d_in[3];              // int32 or int64 — k0 autodetects
    float*       out  = (float*)d_out;

    k0_pt<<<1, 256>>>(pt);
    k1_xfft<<<BATCHN * INF, 256>>>(x);
    k2_kfft<<<FEAT * INF, 256>>>(kern);
    dim3 g3(NFREQ, FQD / 64);
    k3_gemm<<<g3, 256>>>();
    k4_inv<<<BATCHN * FEAT, 256>>>(bias, out);
}

// round 9
// speedup vs baseline: 1.3308x; 1.3308x over previous
#include <cuda_runtime.h>
#include <cstdint>

#define BATCHN 64
#define FEAT   64
#define INF    64
#define NP     8
#define NCELL  256
#define NSYM   2048
#define NK2    9          // rfft half-plane: k2 in [0,8]
#define NFREQ  144        // 16 * 9
#define IPD    512        // INF * NP
#define FQD    512        // FEAT * NP

// -------- device scratch (no dynamic allocation allowed) --------
__device__ float2 g_xf[(size_t)NFREQ * BATCHN * IPD];   // [k][b][ip]
__device__ float2 g_kf[(size_t)NFREQ * IPD * FQD];      // [k][ip][fq]  (~302 MB)
__device__ float2 g_yf[(size_t)NFREQ * BATCHN * FQD];   // [k][b][fq]
__device__ unsigned short g_pt16[NP * NSYM];

// cos/sin of 2*pi*m/16
__constant__ float CTW16[16] = {
    1.0f,  0.92387953251f,  0.70710678119f,  0.38268343236f,
    0.0f, -0.38268343236f, -0.70710678119f, -0.92387953251f,
   -1.0f, -0.92387953251f, -0.70710678119f, -0.38268343236f,
    0.0f,  0.38268343236f,  0.70710678119f,  0.92387953251f };
__constant__ float STW16[16] = {
    0.0f,  0.38268343236f,  0.70710678119f,  0.92387953251f,
    1.0f,  0.92387953251f,  0.70710678119f,  0.38268343236f,
    0.0f, -0.38268343236f, -0.70710678119f, -0.92387953251f,
   -1.0f, -0.92387953251f, -0.70710678119f, -0.38268343236f };

// ============ K0: product_table (int32 OR int64) -> uint16 ============
__global__ __launch_bounds__(256) void k0_pt(const void* __restrict__ pt_raw) {
    __shared__ int odd_nonzero;
    const int* p32 = (const int*)pt_raw;
    int tid = threadIdx.x;
    if (tid == 0) odd_nonzero = 0;
    __syncthreads();
    int local = 0;
    for (int t = tid; t < (NP * NSYM) / 2; t += 256) local |= p32[2 * t + 1];
    if (local) odd_nonzero = 1;   // benign race: any writer sets 1
    __syncthreads();
    if (odd_nonzero) {            // int32 layout
        for (int t = tid; t < NP * NSYM; t += 256)
            g_pt16[t] = (unsigned short)p32[t];
    } else {                      // genuine int64 layout
        const long long* p64 = (const long long*)pt_raw;
        for (int t = tid; t < NP * NSYM; t += 256)
            g_pt16[t] = (unsigned short)p64[t];
    }
}

// ============ K1: forward rfft2 of x images ============
__global__ __launch_bounds__(256) void k1_xfft(const float* __restrict__ x) {
    int bi = blockIdx.x;
    int b  = bi >> 6;
    int i  = bi & 63;
    __shared__ float  xs[NSYM];
    __shared__ float2 s1[NP * 145];
    __shared__ float2 tw[16];
    int tid = threadIdx.x;
    if (tid < 16) tw[tid] = make_float2(CTW16[tid], STW16[tid]);
    for (int t = tid; t < NSYM; t += 256) xs[t] = x[(size_t)bi * NSYM + t];
    __syncthreads();

    for (int idx = tid; idx < NP * 16 * NK2; idx += 256) {
        int p  = idx / 144;
        int r  = idx - p * 144;
        int c1 = r / 9;
        int k2 = r - c1 * 9;
        float2 acc = make_float2(0.f, 0.f);
#pragma unroll
        for (int c2 = 0; c2 < 16; c2++) {
            float  g = xs[(((c1 << 4) + c2) << 3) + p];
            float2 w = tw[(k2 * c2) & 15];
            acc.x += g * w.x;
            acc.y -= g * w.y;
        }
        s1[p * 145 + c1 * 9 + k2] = acc;
    }
    __syncthreads();

    for (int idx = tid; idx < NP * 16 * NK2; idx += 256) {
        int p  = idx & 7;
        int r  = idx >> 3;
        int k1 = r / 9;
        int k2 = r - k1 * 9;
        float2 acc = make_float2(0.f, 0.f);
#pragma unroll
        for (int c1 = 0; c1 < 16; c1++) {
            float2 v = s1[p * 145 + c1 * 9 + k2];
            float2 w = tw[(k1 * c1) & 15];
            acc.x += v.x * w.x + v.y * w.y;
            acc.y += v.y * w.x - v.x * w.y;
        }
        g_xf[((size_t)(k1 * 9 + k2) * BATCHN + b) * IPD + (i << 3) + p] = acc;
    }
}

// ============ K2: gather + forward rfft2 of kernel images ============
__global__ __launch_bounds__(256) void k2_kfft(const float* __restrict__ kern) {
    int fi = blockIdx.x;
    int f  = fi >> 6;
    int i  = fi & 63;
    __shared__ float  krow[NSYM];
    __shared__ unsigned short ptp[NSYM];
    __shared__ float  g8[NP * NCELL];
    __shared__ float2 s1[NP * 145];
    __shared__ float2 tw[16];
    int tid = threadIdx.x;
    if (tid < 16) tw[tid] = make_float2(CTW16[tid], STW16[tid]);
    for (int t = tid; t < NSYM; t += 256) krow[t] = kern[(size_t)fi * NSYM + t];

    for (int p = 0; p < NP; p++) {
        __syncthreads();
        for (int t = tid; t < NSYM; t += 256) ptp[t] = g_pt16[p * NSYM + t];
        __syncthreads();
        for (int idx = tid; idx < NSYM; idx += 256) {
            int d = idx >> 3;
            int q = idx & 7;
            g8[q * NCELL + d] = krow[ptp[idx]];
        }
        __syncthreads();
        for (int idx = tid; idx < NP * 16 * NK2; idx += 256) {
            int q  = idx / 144;
            int r  = idx - q * 144;
            int c1 = r / 9;
            int k2 = r - c1 * 9;
            float2 acc = make_float2(0.f, 0.f);
#pragma unroll
            for (int c2 = 0; c2 < 16; c2++) {
                float  g = g8[q * NCELL + (c1 << 4) + c2];
                float2 w = tw[(k2 * c2) & 15];
                acc.x += g * w.x;
                acc.y -= g * w.y;
            }
            s1[q * 145 + c1 * 9 + k2] = acc;
        }
        __syncthreads();
        for (int idx = tid; idx < NP * 16 * NK2; idx += 256) {
            int q  = idx & 7;
            int r  = idx >> 3;
            int k1 = r / 9;
            int k2 = r - k1 * 9;
            float2 acc = make_float2(0.f, 0.f);
#pragma unroll
            for (int c1 = 0; c1 < 16; c1++) {
                float2 v = s1[q * 145 + c1 * 9 + k2];
                float2 w = tw[(k1 * c1) & 15];
                acc.x += v.x * w.x + v.y * w.y;
                acc.y += v.y * w.x - v.x * w.y;
            }
            g_kf[((size_t)(k1 * 9 + k2) * IPD + (i << 3) + p) * FQD + (f << 3) + q] = acc;
        }
    }
}

// ============ K3: per-frequency complex GEMM on tensor cores (tf32 mma.sync) ============
// Y[k][b][fq] = sum_ip X[k][b][ip] * W[k][ip][fq]
// grid = (144 freqs, 4 N-tiles of 128). block 256 = 8 warps (4 M x 2 N).
// warp tile: 16 (batch) x 64 (fq) complex. m16n8k8 tf32 fragments.
__device__ __forceinline__ uint32_t f2tf32(float x) {
    uint32_t r;
    asm("cvt.rna.tf32.f32 %0, %1;" : "=r"(r) : "f"(x));
    return r;
}
__device__ __forceinline__ void mma8(float* d, const uint32_t* a, uint32_t b0, uint32_t b1) {
    asm volatile(
        "mma.sync.aligned.m16n8k8.row.col.f32.tf32.tf32.f32 "
        "{%0,%1,%2,%3}, {%4,%5,%6,%7}, {%8,%9}, {%0,%1,%2,%3};\n"
        : "+f"(d[0]), "+f"(d[1]), "+f"(d[2]), "+f"(d[3])
        : "r"(a[0]), "r"(a[1]), "r"(a[2]), "r"(a[3]), "r"(b0), "r"(b1));
}

__global__ __launch_bounds__(256) void k3_gemm_tc() {
    int kidx = blockIdx.x;
    int n0   = blockIdx.y << 7;          // 128-wide N tile
    __shared__ __align__(16) float2 Xs[64][18];   // [b][k] (pad 18: 16B-aligned f4 stores)
    __shared__ __align__(16) float2 Ws[16][130];  // [k][n] (pad 130)

    int tid  = threadIdx.x;
    int wid  = tid >> 5;
    int lane = tid & 31;
    int wm   = (wid & 3) << 4;           // warp M offset: 0,16,32,48
    int wn   = (wid >> 2) << 6;          // warp N offset: 0 or 64
    int gid  = lane >> 2;                // 0..7
    int tig  = lane & 3;                 // 0..3

    float accr[8][4], acci[8][4];
#pragma unroll
    for (int j = 0; j < 8; j++)
#pragma unroll
        for (int c = 0; c < 4; c++) { accr[j][c] = 0.f; acci[j][c] = 0.f; }

    const float4* Xg4 = (const float4*)(g_xf + (size_t)kidx * BATCHN * IPD);
    const float4* Wg4 = (const float4*)(g_kf + (size_t)kidx * IPD * FQD);

    for (int k0 = 0; k0 < IPD; k0 += 16) {
        // stage X: 64 rows x 8 float4 = 512 float4
#pragma unroll
        for (int it = 0; it < 2; it++) {
            int u = tid + (it << 8);
            int b = u >> 3;
            int j = u & 7;
            float4 v = Xg4[(((size_t)b * IPD + k0) >> 1) + j];
            *(float4*)&Xs[b][2 * j] = v;
        }
        // stage W: 16 rows x 64 float4 = 1024 float4
#pragma unroll
        for (int it = 0; it < 4; it++) {
            int u  = tid + (it << 8);
            int kk = u >> 6;
            int j  = u & 63;
            float4 v = Wg4[(((size_t)(k0 + kk) * FQD + n0) >> 1) + j];
            *(float4*)&Ws[kk][2 * j] = v;
        }
        __syncthreads();

#pragma unroll
        for (int ks = 0; ks < 2; ks++) {
            int kc = ks << 3;
            // A fragments (row m, col k) for real and imag parts
            float2 x0 = Xs[wm + gid][kc + tig];
            float2 x1 = Xs[wm + gid + 8][kc + tig];
            float2 x2 = Xs[wm + gid][kc + tig + 4];
            float2 x3 = Xs[wm + gid + 8][kc + tig + 4];
            uint32_t ar[4] = { f2tf32(x0.x), f2tf32(x1.x), f2tf32(x2.x), f2tf32(x3.x) };
            uint32_t ai[4] = { f2tf32(x0.y), f2tf32(x1.y), f2tf32(x2.y), f2tf32(x3.y) };
#pragma unroll
            for (int j = 0; j < 8; j++) {
                // B fragments: b0 (k=kc+tig, n), b1 (k=kc+tig+4, n), n = wn + 8j + gid
                float2 w0 = Ws[kc + tig][wn + (j << 3) + gid];
                float2 w1 = Ws[kc + tig + 4][wn + (j << 3) + gid];
                uint32_t br0 = f2tf32(w0.x), br1 = f2tf32(w1.x);
                uint32_t bi0 = f2tf32(w0.y), bi1 = f2tf32(w1.y);
                uint32_t bn0 = bi0 ^ 0x80000000u, bn1 = bi1 ^ 0x80000000u; // -Bi
                mma8(accr[j], ar, br0, br1);   // Yr += Xr*Wr
                mma8(accr[j], ai, bn0, bn1);   // Yr += Xi*(-Wi)
                mma8(acci[j], ar, bi0, bi1);   // Yi += Xr*Wi
                mma8(acci[j], ai, br0, br1);   // Yi += Xi*Wr
            }
        }
        __syncthreads();
    }

    // epilogue: c0:(row=gid, col=2*tig) c1:(+0,+1) c2:(row+8,2*tig) c3:(+8,+1)
    float2* Yg = g_yf + (size_t)kidx * BATCHN * FQD;
#pragma unroll
    for (int j = 0; j < 8; j++) {
        int nbase = n0 + wn + (j << 3) + 2 * tig;
        int r0 = wm + gid;
        int r1 = wm + gid + 8;
        Yg[(size_t)r0 * FQD + nbase]     = make_float2(accr[j][0], acci[j][0]);
        Yg[(size_t)r0 * FQD + nbase + 1] = make_float2(accr[j][1], acci[j][1]);
        Yg[(size_t)r1 * FQD + nbase]     = make_float2(accr[j][2], acci[j][2]);
        Yg[(size_t)r1 * FQD + nbase + 1] = make_float2(accr[j][3], acci[j][3]);
    }
}

// ============ K4: inverse rfft2 (hermitian weights) + bias ============
__global__ __launch_bounds__(256) void k4_inv(const float* __restrict__ bias,
                                              float* __restrict__ out) {
    int bf = blockIdx.x;
    int b  = bf >> 6;
    int f  = bf & 63;
    __shared__ float2 ys[NP * NFREQ];
    __shared__ float2 T[NP * 145];
    __shared__ float2 tw[16];
    int tid = threadIdx.x;
    if (tid < 16) tw[tid] = make_float2(CTW16[tid], STW16[tid]);

    for (int idx = tid; idx < NP * NFREQ; idx += 256) {
        int kidx = idx >> 3;
        int q    = idx & 7;
        ys[q * NFREQ + kidx] =
            g_yf[((size_t)kidx * BATCHN + b) * FQD + (f << 3) + q];
    }
    __syncthreads();

    for (int idx = tid; idx < NP * 16 * NK2; idx += 256) {
        int q  = idx / 144;
        int r  = idx - q * 144;
        int c1 = r / 9;
        int k2 = r - c1 * 9;
        float2 acc = make_float2(0.f, 0.f);
#pragma unroll
        for (int k1 = 0; k1 < 16; k1++) {
            float2 v = ys[q * NFREQ + k1 * 9 + k2];
            float2 w = tw[(k1 * c1) & 15];
            acc.x += v.x * w.x - v.y * w.y;
            acc.y += v.x * w.y + v.y * w.x;
        }
        T[q * 145 + c1 * 9 + k2] = acc;
    }
    __syncthreads();

    float bv = bias[f];
    for (int idx = tid; idx < NSYM; idx += 256) {
        int c  = idx >> 3;
        int q  = idx & 7;
        int c1 = c >> 4;
        int c2 = c & 15;
        float acc = 0.f;
#pragma unroll
        for (int k2 = 0; k2 < NK2; k2++) {
            float2 v  = T[q * 145 + c1 * 9 + k2];
            float2 w  = tw[(k2 * c2) & 15];
            float  wt = (k2 == 0 || k2 == 8) ? 1.f : 2.f;
            acc += wt * (v.x * w.x - v.y * w.y);
        }
        out[(size_t)bf * NSYM + idx] = acc * (1.f / 256.f) + bv;
    }
}

// ============ launch ============
extern "C" void kernel_launch(void* const* d_in, const int* in_sizes, int n_in,
                              void* d_out, int out_size) {
    const float* x    = (const float*)d_in[0];
    const float* kern = (const float*)d_in[1];
    const float* bias = (const float*)d_in[2];
    const void*  pt   = d_in[3];              // int32 or int64 — k0 autodetects
    float*       out  = (float*)d_out;

    k0_pt<<<1, 256>>>(pt);
    k1_xfft<<<BATCHN * INF, 256>>>(x);
    k2_kfft<<<FEAT * INF, 256>>>(kern);
    dim3 g3(NFREQ, FQD / 128);
    k3_gemm_tc<<<g3, 256>>>();
    k4_inv<<<BATCHN * FEAT, 256>>>(bias, out);
}

// round 11
// speedup vs baseline: 2.3080x; 1.7343x over previous
#include <cuda_runtime.h>
#include <cuda_fp16.h>
#include <cstdint>

#define BATCHN 64
#define FEAT   64
#define INF    64
#define NP     8
#define NCELL  256
#define NSYM   2048
#define NK2    9          // rfft half-plane: k2 in [0,8]
#define NFREQ  144        // 16 * 9
#define IPD    512        // INF * NP
#define FQD    512        // FEAT * NP

// -------- device scratch (no dynamic allocation allowed) --------
__device__ __half2 g_xf[(size_t)NFREQ * BATCHN * IPD];   // [k][b][ip] (re,im) fp16
__device__ __half2 g_kf[(size_t)NFREQ * IPD * FQD];      // [k][ip][fq] (~151 MB)
__device__ float2  g_yf[(size_t)NFREQ * BATCHN * FQD];   // [k][b][fq]
__device__ unsigned short g_pt16[NP * NSYM];

// cos/sin of 2*pi*m/16 — __device__ constexpr: folded to FFMA immediates
__device__ constexpr float KC16[16] = {
    1.0f,  0.92387953251f,  0.70710678119f,  0.38268343236f,
    0.0f, -0.38268343236f, -0.70710678119f, -0.92387953251f,
   -1.0f, -0.92387953251f, -0.70710678119f, -0.38268343236f,
    0.0f,  0.38268343236f,  0.70710678119f,  0.92387953251f };
__device__ constexpr float KS16[16] = {
    0.0f,  0.38268343236f,  0.70710678119f,  0.92387953251f,
    1.0f,  0.92387953251f,  0.70710678119f,  0.38268343236f,
    0.0f, -0.38268343236f, -0.70710678119f, -0.92387953251f,
   -1.0f, -0.92387953251f, -0.70710678119f, -0.38268343236f };

// runtime copies for k1/k4 (dynamic twiddle indexing there)
__constant__ float CTW16[16] = {
    1.0f,  0.92387953251f,  0.70710678119f,  0.38268343236f,
    0.0f, -0.38268343236f, -0.70710678119f, -0.92387953251f,
   -1.0f, -0.92387953251f, -0.70710678119f, -0.38268343236f,
    0.0f,  0.38268343236f,  0.70710678119f,  0.92387953251f };
__constant__ float STW16[16] = {
    0.0f,  0.38268343236f,  0.70710678119f,  0.92387953251f,
    1.0f,  0.92387953251f,  0.70710678119f,  0.38268343236f,
    0.0f, -0.38268343236f, -0.70710678119f, -0.92387953251f,
   -1.0f, -0.92387953251f, -0.70710678119f, -0.38268343236f };

// ============ K0: product_table (int32 OR int64) -> uint16 ============
__global__ __launch_bounds__(256) void k0_pt(const void* __restrict__ pt_raw) {
    __shared__ int odd_nonzero;
    const int* p32 = (const int*)pt_raw;
    int tid = threadIdx.x;
    if (tid == 0) odd_nonzero = 0;
    __syncthreads();
    int local = 0;
    for (int t = tid; t < (NP * NSYM) / 2; t += 256) local |= p32[2 * t + 1];
    if (local) odd_nonzero = 1;
    __syncthreads();
    if (odd_nonzero) {
        for (int t = tid; t < NP * NSYM; t += 256)
            g_pt16[t] = (unsigned short)p32[t];
    } else {
        const long long* p64 = (const long long*)pt_raw;
        for (int t = tid; t < NP * NSYM; t += 256)
            g_pt16[t] = (unsigned short)p64[t];
    }
}

// ============ K1: forward rfft2 of x images (half2 output) ============
__global__ __launch_bounds__(256) void k1_xfft(const float* __restrict__ x) {
    int bi = blockIdx.x;
    int b  = bi >> 6;
    int i  = bi & 63;
    __shared__ float  xs[NSYM];
    __shared__ float2 s1[NP * 145];
    __shared__ float2 tw[16];
    int tid = threadIdx.x;
    if (tid < 16) tw[tid] = make_float2(CTW16[tid], STW16[tid]);
    for (int t = tid; t < NSYM; t += 256) xs[t] = x[(size_t)bi * NSYM + t];
    __syncthreads();

    for (int idx = tid; idx < NP * 16 * NK2; idx += 256) {
        int p  = idx / 144;
        int r  = idx - p * 144;
        int c1 = r / 9;
        int k2 = r - c1 * 9;
        float2 acc = make_float2(0.f, 0.f);
#pragma unroll
        for (int c2 = 0; c2 < 16; c2++) {
            float  g = xs[(((c1 << 4) + c2) << 3) + p];
            float2 w = tw[(k2 * c2) & 15];
            acc.x += g * w.x;
            acc.y -= g * w.y;
        }
        s1[p * 145 + c1 * 9 + k2] = acc;
    }
    __syncthreads();

    for (int idx = tid; idx < NP * 16 * NK2; idx += 256) {
        int p  = idx & 7;
        int r  = idx >> 3;
        int k1 = r / 9;
        int k2 = r - k1 * 9;
        float2 acc = make_float2(0.f, 0.f);
#pragma unroll
        for (int c1 = 0; c1 < 16; c1++) {
            float2 v = s1[p * 145 + c1 * 9 + k2];
            float2 w = tw[(k1 * c1) & 15];
            acc.x += v.x * w.x + v.y * w.y;
            acc.y += v.y * w.x - v.x * w.y;
        }
        g_xf[((size_t)(k1 * 9 + k2) * BATCHN + b) * IPD + (i << 3) + p] =
            __floats2half2_rn(acc.x, acc.y);
    }
}

// ============ K2: gather + forward rfft2, register-blocked, fp16 out ============
// block = (f, i); per p: gather, stage1 (static k2-halves), stage2 (static k1-quarters)
#define K2S2BODY(K1Q)                                                        \
    _Pragma("unroll")                                                        \
    for (int c1 = 0; c1 < 16; c1++) {                                        \
        _Pragma("unroll")                                                    \
        for (int kk = 0; kk < 4; kk++) {                                     \
            const int id = ((((K1Q) * 4 + kk) * c1) & 15);                   \
            br[kk] += vv[c1].x * KC16[id] + vv[c1].y * KS16[id];             \
            bi[kk] += vv[c1].y * KC16[id] - vv[c1].x * KS16[id];             \
        }                                                                    \
    }

__global__ __launch_bounds__(256) void k2_kfft(const float* __restrict__ kern) {
    int fi = blockIdx.x, f = fi >> 6, i = fi & 63;
    __shared__ float krow[NSYM];
    __shared__ unsigned short ptp[NSYM];
    __shared__ float  g8[NP][264];     // [q][d], pad 264 (16B-aligned rows)
    __shared__ float2 s1[NP][145];     // [q][c1*9+k2]
    int tid = threadIdx.x;
    for (int t = tid; t < NSYM; t += 256) krow[t] = kern[(size_t)fi * NSYM + t];

    for (int p = 0; p < NP; p++) {
        __syncthreads();
        // ptp: 2048 u16 = 256 uint4, one per thread
        ((uint4*)ptp)[tid] = ((const uint4*)(g_pt16 + p * NSYM))[tid];
        __syncthreads();
        // gather: g8[q][d] = krow[pt[p][d*8+q]]
        for (int idx = tid; idx < NSYM; idx += 256)
            g8[idx & 7][idx >> 3] = krow[ptp[idx]];
        __syncthreads();
        // ---- stage1: thread = (k2half, q, c1); fully static twiddles ----
        {
            int k2h = tid >> 7, q = (tid >> 4) & 7, c1 = tid & 15;
            const float4* gp = (const float4*)&g8[q][c1 * 16];
            float4 ga = gp[0], gb = gp[1], gc = gp[2], gd = gp[3];
            float g[16] = { ga.x, ga.y, ga.z, ga.w, gb.x, gb.y, gb.z, gb.w,
                            gc.x, gc.y, gc.z, gc.w, gd.x, gd.y, gd.z, gd.w };
            if (k2h == 0) {
                float ar[5] = {0,0,0,0,0}, ai[5] = {0,0,0,0,0};
#pragma unroll
                for (int c2 = 0; c2 < 16; c2++) {
#pragma unroll
                    for (int t = 0; t < 5; t++) {
                        const int id = ((t * c2) & 15);
                        ar[t] += g[c2] * KC16[id];
                        ai[t] -= g[c2] * KS16[id];
                    }
                }
#pragma unroll
                for (int t = 0; t < 5; t++)
                    s1[q][c1 * 9 + t] = make_float2(ar[t], ai[t]);
            } else {
                float ar[4] = {0,0,0,0}, ai[4] = {0,0,0,0};
#pragma unroll
                for (int c2 = 0; c2 < 16; c2++) {
#pragma unroll
                    for (int t = 0; t < 4; t++) {
                        const int id = (((t + 5) * c2) & 15);
                        ar[t] += g[c2] * KC16[id];
                        ai[t] -= g[c2] * KS16[id];
                    }
                }
#pragma unroll
                for (int t = 0; t < 4; t++)
                    s1[q][c1 * 9 + 5 + t] = make_float2(ar[t], ai[t]);
            }
        }
        __syncthreads();
        // ---- stage2: item = (q, k2, k1-quarter); static twiddles per branch ----
        for (int u = tid; u < 288; u += 256) {
            int q = u & 7, v = u >> 3;
            int k2 = v % 9, k1q = v / 9;
            float2 vv[16];
#pragma unroll
            for (int c1 = 0; c1 < 16; c1++) vv[c1] = s1[q][c1 * 9 + k2];
            float br[4] = {0,0,0,0}, bi[4] = {0,0,0,0};
            if      (k1q == 0) { K2S2BODY(0) }
            else if (k1q == 1) { K2S2BODY(1) }
            else if (k1q == 2) { K2S2BODY(2) }
            else               { K2S2BODY(3) }
#pragma unroll
            for (int kk = 0; kk < 4; kk++) {
                int k1 = k1q * 4 + kk;
                g_kf[((size_t)(k1 * 9 + k2) * IPD + (i << 3) + p) * FQD + (f << 3) + q] =
                    __floats2half2_rn(br[kk], bi[kk]);
            }
        }
    }
}

// ============ K3: per-frequency complex GEMM, fp16 mma (m16n8k16) ============
// grid = (144 freqs, 4 N-tiles of 128). block 256 = 8 warps (4 M x 2 N).
__device__ __forceinline__ void mma16(float* d, const uint32_t* a,
                                      uint32_t b0, uint32_t b1) {
    asm volatile(
        "mma.sync.aligned.m16n8k16.row.col.f32.f16.f16.f32 "
        "{%0,%1,%2,%3}, {%4,%5,%6,%7}, {%8,%9}, {%0,%1,%2,%3};\n"
        : "+f"(d[0]), "+f"(d[1]), "+f"(d[2]), "+f"(d[3])
        : "r"(a[0]), "r"(a[1]), "r"(a[2]), "r"(a[3]), "r"(b0), "r"(b1));
}

__global__ __launch_bounds__(256) void k3_gemm_hmma() {
    int kidx = blockIdx.x;
    int n0   = blockIdx.y << 7;
    __shared__ __align__(16) __half2 Xs[64][20];    // [b][k] interleaved (re,im)
    __shared__ __align__(16) __half2 Ws[16][132];   // [k][n] interleaved

    int tid = threadIdx.x, wid = tid >> 5, lane = tid & 31;
    int wm = (wid & 3) << 4, wn = (wid >> 2) << 6;
    int gid = lane >> 2, tig = lane & 3;

    float accr[8][4], acci[8][4];
#pragma unroll
    for (int j = 0; j < 8; j++)
#pragma unroll
        for (int c = 0; c < 4; c++) { accr[j][c] = 0.f; acci[j][c] = 0.f; }

    for (int k0 = 0; k0 < IPD; k0 += 16) {
        // stage X: 64 rows x 4 uint4 (16 half2 per row)
        {
            int b = tid >> 2, seg = tid & 3;
            uint4 v = *(const uint4*)&g_xf[(size_t)kidx * BATCHN * IPD + (size_t)b * IPD + k0 + seg * 4];
            *(uint4*)&Xs[b][seg * 4] = v;
        }
        // stage W: 16 rows x 32 uint4
#pragma unroll
        for (int it = 0; it < 2; it++) {
            int v  = tid + (it << 8);
            int kk = v >> 5, seg = v & 31;
            uint4 w = *(const uint4*)&g_kf[((size_t)kidx * IPD + k0 + kk) * FQD + n0 + seg * 4];
            *(uint4*)&Ws[kk][seg * 4] = w;
        }
        __syncthreads();

        // A fragments (re/im split via byte_perm)
        uint32_t arf[4], aif[4];
#pragma unroll
        for (int m = 0; m < 4; m++) {
            int row  = wm + gid + (m & 1) * 8;
            int kpos = 2 * tig + (m >> 1) * 8;
            uint2 lh = *(const uint2*)&Xs[row][kpos];   // (k, k+1) interleaved
            arf[m] = __byte_perm(lh.x, lh.y, 0x5410);   // re(k), re(k+1)
            aif[m] = __byte_perm(lh.x, lh.y, 0x7632);   // im(k), im(k+1)
        }
#pragma unroll
        for (int j = 0; j < 8; j++) {
            int col = wn + (j << 3) + gid;
            uint32_t v0 = *(const uint32_t*)&Ws[2 * tig][col];
            uint32_t v1 = *(const uint32_t*)&Ws[2 * tig + 1][col];
            uint32_t v2 = *(const uint32_t*)&Ws[2 * tig + 8][col];
            uint32_t v3 = *(const uint32_t*)&Ws[2 * tig + 9][col];
            uint32_t br0 = __byte_perm(v0, v1, 0x5410), bi0 = __byte_perm(v0, v1, 0x7632);
            uint32_t br1 = __byte_perm(v2, v3, 0x5410), bi1 = __byte_perm(v2, v3, 0x7632);
            uint32_t bn0 = bi0 ^ 0x80008000u, bn1 = bi1 ^ 0x80008000u;   // -Wi
            mma16(accr[j], arf, br0, br1);   // Yr += Xr*Wr
            mma16(accr[j], aif, bn0, bn1);   // Yr += Xi*(-Wi)
            mma16(acci[j], arf, bi0, bi1);   // Yi += Xr*Wi
            mma16(acci[j], aif, br0, br1);   // Yi += Xi*Wr
        }
        __syncthreads();
    }

    float2* Yg = g_yf + (size_t)kidx * BATCHN * FQD;
#pragma unroll
    for (int j = 0; j < 8; j++) {
        int nbase = n0 + wn + (j << 3) + 2 * tig;
        int r0 = wm + gid;
        int r1 = wm + gid + 8;
        Yg[(size_t)r0 * FQD + nbase]     = make_float2(accr[j][0], acci[j][0]);
        Yg[(size_t)r0 * FQD + nbase + 1] = make_float2(accr[j][1], acci[j][1]);
        Yg[(size_t)r1 * FQD + nbase]     = make_float2(accr[j][2], acci[j][2]);
        Yg[(size_t)r1 * FQD + nbase + 1] = make_float2(accr[j][3], acci[j][3]);
    }
}

// ============ K4: inverse rfft2 (hermitian weights) + bias ============
__global__ __launch_bounds__(256) void k4_inv(const float* __restrict__ bias,
                                              float* __restrict__ out) {
    int bf = blockIdx.x;
    int b  = bf >> 6;
    int f  = bf & 63;
    __shared__ float2 ys[NP * NFREQ];
    __shared__ float2 T[NP * 145];
    __shared__ float2 tw[16];
    int tid = threadIdx.x;
    if (tid < 16) tw[tid] = make_float2(CTW16[tid], STW16[tid]);

    for (int idx = tid; idx < NP * NFREQ; idx += 256) {
        int kidx = idx >> 3;
        int q    = idx & 7;
        ys[q * NFREQ + kidx] =
            g_yf[((size_t)kidx * BATCHN + b) * FQD + (f << 3) + q];
    }
    __syncthreads();

    for (int idx = tid; idx < NP * 16 * NK2; idx += 256) {
        int q  = idx / 144;
        int r  = idx - q * 144;
        int c1 = r / 9;
        int k2 = r - c1 * 9;
        float2 acc = make_float2(0.f, 0.f);
#pragma unroll
        for (int k1 = 0; k1 < 16; k1++) {
            float2 v = ys[q * NFREQ + k1 * 9 + k2];
            float2 w = tw[(k1 * c1) & 15];
            acc.x += v.x * w.x - v.y * w.y;
            acc.y += v.x * w.y + v.y * w.x;
        }
        T[q * 145 + c1 * 9 + k2] = acc;
    }
    __syncthreads();

    float bv = bias[f];
    for (int idx = tid; idx < NSYM; idx += 256) {
        int c  = idx >> 3;
        int q  = idx & 7;
        int c1 = c >> 4;
        int c2 = c & 15;
        float acc = 0.f;
#pragma unroll
        for (int k2 = 0; k2 < NK2; k2++) {
            float2 v  = T[q * 145 + c1 * 9 + k2];
            float2 w  = tw[(k2 * c2) & 15];
            float  wt = (k2 == 0 || k2 == 8) ? 1.f : 2.f;
            acc += wt * (v.x * w.x - v.y * w.y);
        }
        out[(size_t)bf * NSYM + idx] = acc * (1.f / 256.f) + bv;
    }
}

// ============ launch ============
extern "C" void kernel_launch(void* const* d_in, const int* in_sizes, int n_in,
                              void* d_out, int out_size) {
    const float* x    = (const float*)d_in[0];
    const float* kern = (const float*)d_in[1];
    const float* bias = (const float*)d_in[2];
    const void*  pt   = d_in[3];              // int32 or int64 — k0 autodetects
    float*       out  = (float*)d_out;

    k0_pt<<<1, 256>>>(pt);
    k1_xfft<<<BATCHN * INF, 256>>>(x);
    k2_kfft<<<FEAT * INF, 256>>>(kern);
    dim3 g3(NFREQ, FQD / 128);
    k3_gemm_hmma<<<g3, 256>>>();
    k4_inv<<<BATCHN * FEAT, 256>>>(bias, out);
}